// round 1
// baseline (speedup 1.0000x reference)
#include <cuda_runtime.h>
#include <math.h>

// Problem dims
#define H   256
#define H2  512
#define H3  768
#define B   64
#define L   2048
#define V   32000
#define YPITCH 516          // padded pitch for y = [h_new, ctx]
#define VT  32              // v-tile per block in logits kernel

// ---------------- scratch (device globals; no allocation allowed) ----------------
__device__ __align__(16) float g_w2[H2];        // attn_W^T @ flatten
__device__ __align__(16) float g_ehb[B];        // e_h[b] + bias_term
__device__ __align__(16) float g_emb[B * H];    // embedded
__device__ __align__(16) float g_attn[B * L];   // energies -> softmax weights (in place)
__device__ __align__(16) float g_ctx[B * H];    // context (atomic-accumulated)
__device__ __align__(16) float g_gi[B * H3];
__device__ __align__(16) float g_gh[B * H3];
__device__ __align__(16) float g_y[B * YPITCH]; // [h_new ; ctx] padded
__device__ __align__(16) float g_logits[B * V];

// ---------------- K1: w2, bias, e_h+bias, embedding gather, zero ctx -------------
__global__ void k1_prep(const float* __restrict__ attn_W,
                        const float* __restrict__ attn_b,
                        const float* __restrict__ flatten,
                        const float* __restrict__ hidden,
                        const int*   __restrict__ input,
                        const float* __restrict__ emb_table)
{
    __shared__ float s_f[H];
    __shared__ float s_wh[H];
    __shared__ float red[512];
    int tid = threadIdx.x;                      // 512 threads

    if (tid < H) s_f[tid] = flatten[tid];
    __syncthreads();

    // w2[j] = sum_i attn_W[i, j] * f[i]   (attn_W is [H, 2H] row-major)
    float acc = 0.f;
    #pragma unroll 8
    for (int i = 0; i < H; i++) acc += attn_W[i * H2 + tid] * s_f[i];
    g_w2[tid] = acc;
    if (tid < H) s_wh[tid] = acc;               // w2[:H] for e_h

    // bias = f . attn_b
    red[tid] = (tid < H) ? s_f[tid] * attn_b[tid] : 0.f;
    __syncthreads();
    for (int s = 256; s > 0; s >>= 1) {
        if (tid < s) red[tid] += red[tid + s];
        __syncthreads();
    }
    float bias = red[0];

    // e_h[b] = h[b] . w2[:H]; store e_h + bias
    int wid = tid >> 5, lane = tid & 31;        // 16 warps * 4 b each
    #pragma unroll
    for (int i = 0; i < 4; i++) {
        int b = wid * 4 + i;
        float a = 0.f;
        #pragma unroll
        for (int c = 0; c < 8; c++) {
            int k = c * 32 + lane;
            a += hidden[b * H + k] * s_wh[k];
        }
        #pragma unroll
        for (int o = 16; o > 0; o >>= 1) a += __shfl_down_sync(0xffffffffu, a, o);
        if (lane == 0) g_ehb[b] = a + bias;
    }

    // embedded gather + zero ctx
    for (int idx = tid; idx < B * H; idx += 512) {
        int b = idx >> 8;
        g_emb[idx] = emb_table[(size_t)input[b] * H + (idx & 255)];
        g_ctx[idx] = 0.f;
    }
}

// ---------------- K2: energies e[b,l] = enc[l,b,:] . w2[H:] + ehb[b] -------------
__global__ void k2_energy(const float* __restrict__ enc)
{
    int gw   = (blockIdx.x * blockDim.x + threadIdx.x) >> 5;   // warp per (l,b)
    int lane = threadIdx.x & 31;
    int l = gw >> 6;
    int b = gw & 63;
    const float4* e4 = (const float4*)(enc + (size_t)l * B * H + (size_t)b * H);
    const float4* w4 = (const float4*)(g_w2 + H);
    float acc = 0.f;
    #pragma unroll
    for (int c = 0; c < 2; c++) {
        float4 ev = e4[c * 32 + lane];
        float4 wv = w4[c * 32 + lane];
        acc += ev.x * wv.x + ev.y * wv.y + ev.z * wv.z + ev.w * wv.w;
    }
    #pragma unroll
    for (int o = 16; o > 0; o >>= 1) acc += __shfl_down_sync(0xffffffffu, acc, o);
    if (lane == 0) g_attn[b * L + l] = acc + g_ehb[b];
}

// ---------------- K3: softmax over L per batch (in place) ------------------------
__global__ void k3_softmax(float* __restrict__ out_attn)
{
    int b = blockIdx.x, tid = threadIdx.x;      // 256 threads
    __shared__ float red[256];
    float m = -INFINITY;
    for (int i = tid; i < L; i += 256) m = fmaxf(m, g_attn[b * L + i]);
    red[tid] = m; __syncthreads();
    for (int s = 128; s > 0; s >>= 1) {
        if (tid < s) red[tid] = fmaxf(red[tid], red[tid + s]);
        __syncthreads();
    }
    m = red[0]; __syncthreads();

    float sum = 0.f;
    for (int i = tid; i < L; i += 256) sum += __expf(g_attn[b * L + i] - m);
    red[tid] = sum; __syncthreads();
    for (int s = 128; s > 0; s >>= 1) {
        if (tid < s) red[tid] += red[tid + s];
        __syncthreads();
    }
    float inv = 1.f / red[0];

    for (int i = tid; i < L; i += 256) {
        float v = __expf(g_attn[b * L + i] - m) * inv;
        g_attn[b * L + i] = v;
        if (out_attn) out_attn[b * L + i] = v;
    }
}

// ---------------- K4: context[b,h] = sum_l a[b,l] * enc[l,b,h] -------------------
#define NCH 32              // l-chunks of 64
__global__ void k4_context(const float* __restrict__ enc)
{
    int b = blockIdx.x / NCH;
    int c = blockIdx.x % NCH;
    int h = threadIdx.x;                        // 256 threads
    __shared__ float s_a[64];
    int l0 = c * 64;
    if (h < 64) s_a[h] = g_attn[b * L + l0 + h];
    __syncthreads();

    const float* base = enc + (size_t)l0 * B * H + (size_t)b * H + h;
    float acc = 0.f;
    #pragma unroll 8
    for (int i = 0; i < 64; i++) acc += s_a[i] * base[(size_t)i * B * H];
    atomicAdd(&g_ctx[b * H + h], acc);
}

// ---------------- K5: GRU matvecs gi, gh (warp per (j,b)) ------------------------
__global__ void k5_gru(const float* __restrict__ Wih, const float* __restrict__ Whh,
                       const float* __restrict__ bih, const float* __restrict__ bhh,
                       const float* __restrict__ hidden)
{
    int gw   = (blockIdx.x * blockDim.x + threadIdx.x) >> 5;
    int lane = threadIdx.x & 31;
    int j = gw >> 6;        // consecutive warps share j -> weight rows hit L1/L2
    int b = gw & 63;

    const float* wi = Wih + (size_t)j * H2;
    const float* wh = Whh + (size_t)j * H;
    float a1 = 0.f, a2 = 0.f;
    #pragma unroll
    for (int c = 0; c < 8; c++) {
        int k = c * 32 + lane;
        a1 += wi[k]     * g_emb[b * H + k];
        a1 += wi[H + k] * g_ctx[b * H + k];
        a2 += wh[k]     * hidden[b * H + k];
    }
    #pragma unroll
    for (int o = 16; o > 0; o >>= 1) {
        a1 += __shfl_down_sync(0xffffffffu, a1, o);
        a2 += __shfl_down_sync(0xffffffffu, a2, o);
    }
    if (lane == 0) {
        g_gi[b * H3 + j] = a1 + bih[j];
        g_gh[b * H3 + j] = a2 + bhh[j];
    }
}

// ---------------- K6: gates + h_new + build y = [h_new; ctx] ---------------------
__global__ void k6_gates(const float* __restrict__ hidden, float* __restrict__ out_h)
{
    int idx = blockIdx.x * 256 + threadIdx.x;   // B*H threads
    int b = idx >> 8, j = idx & 255;
    float gir = g_gi[b * H3 + j],          ghr = g_gh[b * H3 + j];
    float giz = g_gi[b * H3 + H + j],      ghz = g_gh[b * H3 + H + j];
    float gin = g_gi[b * H3 + 2 * H + j],  ghn = g_gh[b * H3 + 2 * H + j];
    float r = 1.f / (1.f + __expf(-(gir + ghr)));
    float z = 1.f / (1.f + __expf(-(giz + ghz)));
    float n = tanhf(gin + r * ghn);
    float hn = (1.f - z) * n + z * hidden[idx];
    if (out_h) out_h[idx] = hn;
    g_y[b * YPITCH + j]     = hn;
    g_y[b * YPITCH + H + j] = g_ctx[idx];
}

// ---------------- K7: logits[b,v] = y[b,:] . out_W[v,:] + out_b[v] ---------------
// Block: VT=32 v-rows x all 64 b. y (132KB) staged in dynamic smem.
// Thread (tb,tv): 4 b x 2 v register tile. out_W streamed from global (read once).
__global__ __launch_bounds__(256) void k7_logits(const float* __restrict__ outW,
                                                 const float* __restrict__ outb)
{
    extern __shared__ float s_y[];              // B * YPITCH floats
    int tid = threadIdx.x;
    {
        const float4* src = (const float4*)g_y;
        float4* dst = (float4*)s_y;
        for (int i = tid; i < B * YPITCH / 4; i += 256) dst[i] = src[i];
    }
    __syncthreads();

    int tb = tid & 15;
    int tv = tid >> 4;
    int v0 = blockIdx.x * VT + tv * 2;
    const float4* w0 = (const float4*)(outW + (size_t)v0 * H2);
    const float4* w1 = (const float4*)(outW + (size_t)(v0 + 1) * H2);

    float acc0[4] = {0.f, 0.f, 0.f, 0.f};
    float acc1[4] = {0.f, 0.f, 0.f, 0.f};

    #pragma unroll 4
    for (int q = 0; q < H2 / 4; q++) {
        float4 wa = w0[q];
        float4 wb = w1[q];
        #pragma unroll
        for (int i = 0; i < 4; i++) {
            const float4 yv = *(const float4*)(s_y + (tb * 4 + i) * YPITCH + q * 4);
            acc0[i] += yv.x * wa.x + yv.y * wa.y + yv.z * wa.z + yv.w * wa.w;
            acc1[i] += yv.x * wb.x + yv.y * wb.y + yv.z * wb.z + yv.w * wb.w;
        }
    }
    float b0 = outb[v0], b1 = outb[v0 + 1];
    #pragma unroll
    for (int i = 0; i < 4; i++) {
        int b = tb * 4 + i;
        g_logits[(size_t)b * V + v0]     = acc0[i] + b0;
        g_logits[(size_t)b * V + v0 + 1] = acc1[i] + b1;
    }
}

// ---------------- K8: log_softmax over V per batch --------------------------------
__global__ void k8_logsoftmax(float* __restrict__ out)
{
    int b = blockIdx.x, tid = threadIdx.x;      // 512 threads
    __shared__ float red[512];
    const float* row = g_logits + (size_t)b * V;

    float m = -INFINITY;
    for (int i = tid; i < V; i += 512) m = fmaxf(m, row[i]);
    red[tid] = m; __syncthreads();
    for (int s = 256; s > 0; s >>= 1) {
        if (tid < s) red[tid] = fmaxf(red[tid], red[tid + s]);
        __syncthreads();
    }
    m = red[0]; __syncthreads();

    float sum = 0.f;
    for (int i = tid; i < V; i += 512) sum += __expf(row[i] - m);
    red[tid] = sum; __syncthreads();
    for (int s = 256; s > 0; s >>= 1) {
        if (tid < s) red[tid] += red[tid + s];
        __syncthreads();
    }
    float lse = m + logf(red[0]);

    float* orow = out + (size_t)b * V;
    for (int i = tid; i < V; i += 512) orow[i] = row[i] - lse;
}

// ---------------- host launch ------------------------------------------------------
extern "C" void kernel_launch(void* const* d_in, const int* in_sizes, int n_in,
                              void* d_out, int out_size)
{
    // Input order per setup_inputs; slot 3 is the scalar use_cuda (size 1).
    // Be defensive in case the scalar was dropped from the input list.
    int s = (n_in >= 14 && in_sizes[3] == 1) ? 0 : -1;
    const int*   input    = (const int*)  d_in[0];
    const float* hidden   = (const float*)d_in[1];
    const float* enc      = (const float*)d_in[2];
    const float* emb      = (const float*)d_in[4 + s];
    const float* attn_W   = (const float*)d_in[5 + s];
    const float* attn_b   = (const float*)d_in[6 + s];
    const float* flatten  = (const float*)d_in[7 + s];
    const float* Wih      = (const float*)d_in[8 + s];
    const float* Whh      = (const float*)d_in[9 + s];
    const float* bih      = (const float*)d_in[10 + s];
    const float* bhh      = (const float*)d_in[11 + s];
    const float* outW     = (const float*)d_in[12 + s];
    const float* outb     = (const float*)d_in[13 + s];

    float* dout     = (float*)d_out;
    float* out_h    = (out_size >= B * V + B * H) ? dout + B * V : nullptr;
    float* out_attn = (out_size >= B * V + B * H + B * L) ? dout + B * V + B * H : nullptr;

    k1_prep<<<1, 512>>>(attn_W, attn_b, flatten, hidden, input, emb);
    k2_energy<<<(L * B) / 8, 256>>>(enc);
    k3_softmax<<<B, 256>>>(out_attn);
    k4_context<<<B * NCH, 256>>>(enc);
    k5_gru<<<(B * H3) / 8, 256>>>(Wih, Whh, bih, bhh, hidden);
    k6_gates<<<(B * H) / 256, 256>>>(hidden, out_h);

    int smem_k7 = B * YPITCH * (int)sizeof(float);  // 132096 B
    cudaFuncSetAttribute(k7_logits, cudaFuncAttributeMaxDynamicSharedMemorySize, smem_k7);
    k7_logits<<<V / VT, 256, smem_k7>>>(outW, outb);

    k8_logsoftmax<<<B, 512>>>(dout);
}

// round 2
// speedup vs baseline: 1.9958x; 1.9958x over previous
#include <cuda_runtime.h>
#include <math.h>

// Problem dims
#define H   256
#define H2  512
#define H3  768
#define B   64
#define L   2048
#define V   32000

typedef unsigned long long ull;

// ---------------- scratch (device globals; no allocation allowed) ----------------
__device__ __align__(16) float g_w2[H2];        // attn_W^T @ flatten
__device__ __align__(16) float g_ehb[B];        // e_h[b] + bias_term
__device__ __align__(16) float g_emb[B * H];    // embedded
__device__ __align__(16) float g_attn[B * L];   // energies -> softmax weights (in place)
__device__ __align__(16) float g_ctx[B * H];    // context (atomic-accumulated)
__device__ __align__(16) float g_gi[B * H3];
__device__ __align__(16) float g_gh[B * H3];
__device__ __align__(16) float g_yT[H2 * B];    // y transposed: [k][b], k<512, b<64
__device__ __align__(16) float g_logits[B * V];

// ---------------- K1: w2, bias, e_h+bias, embedding gather, zero ctx -------------
__global__ void k1_prep(const float* __restrict__ attn_W,
                        const float* __restrict__ attn_b,
                        const float* __restrict__ flatten,
                        const float* __restrict__ hidden,
                        const int*   __restrict__ input,
                        const float* __restrict__ emb_table)
{
    __shared__ float s_f[H];
    __shared__ float s_wh[H];
    __shared__ float red[512];
    int tid = threadIdx.x;                      // 512 threads

    if (tid < H) s_f[tid] = flatten[tid];
    __syncthreads();

    // w2[j] = sum_i attn_W[i, j] * f[i]   (attn_W is [H, 2H] row-major)
    float acc = 0.f;
    #pragma unroll 8
    for (int i = 0; i < H; i++) acc += attn_W[i * H2 + tid] * s_f[i];
    g_w2[tid] = acc;
    if (tid < H) s_wh[tid] = acc;               // w2[:H] for e_h

    // bias = f . attn_b
    red[tid] = (tid < H) ? s_f[tid] * attn_b[tid] : 0.f;
    __syncthreads();
    for (int s = 256; s > 0; s >>= 1) {
        if (tid < s) red[tid] += red[tid + s];
        __syncthreads();
    }
    float bias = red[0];

    // e_h[b] = h[b] . w2[:H]; store e_h + bias
    int wid = tid >> 5, lane = tid & 31;        // 16 warps * 4 b each
    #pragma unroll
    for (int i = 0; i < 4; i++) {
        int b = wid * 4 + i;
        float a = 0.f;
        #pragma unroll
        for (int c = 0; c < 8; c++) {
            int k = c * 32 + lane;
            a += hidden[b * H + k] * s_wh[k];
        }
        #pragma unroll
        for (int o = 16; o > 0; o >>= 1) a += __shfl_down_sync(0xffffffffu, a, o);
        if (lane == 0) g_ehb[b] = a + bias;
    }

    // embedded gather + zero ctx
    for (int idx = tid; idx < B * H; idx += 512) {
        int b = idx >> 8;
        g_emb[idx] = emb_table[(size_t)input[b] * H + (idx & 255)];
        g_ctx[idx] = 0.f;
    }
}

// ---------------- K2: energies e[b,l] = enc[l,b,:] . w2[H:] + ehb[b] -------------
__global__ void k2_energy(const float* __restrict__ enc)
{
    int gw   = (blockIdx.x * blockDim.x + threadIdx.x) >> 5;   // warp per (l,b)
    int lane = threadIdx.x & 31;
    int l = gw >> 6;
    int b = gw & 63;
    const float4* e4 = (const float4*)(enc + (size_t)l * B * H + (size_t)b * H);
    const float4* w4 = (const float4*)(g_w2 + H);
    float acc = 0.f;
    #pragma unroll
    for (int c = 0; c < 2; c++) {
        float4 ev = e4[c * 32 + lane];
        float4 wv = w4[c * 32 + lane];
        acc += ev.x * wv.x + ev.y * wv.y + ev.z * wv.z + ev.w * wv.w;
    }
    #pragma unroll
    for (int o = 16; o > 0; o >>= 1) acc += __shfl_down_sync(0xffffffffu, acc, o);
    if (lane == 0) g_attn[b * L + l] = acc + g_ehb[b];
}

// ---------------- K3: softmax over L per batch (in place) ------------------------
__global__ void k3_softmax(float* __restrict__ out_attn)
{
    int b = blockIdx.x, tid = threadIdx.x;      // 256 threads
    __shared__ float red[256];
    float m = -INFINITY;
    for (int i = tid; i < L; i += 256) m = fmaxf(m, g_attn[b * L + i]);
    red[tid] = m; __syncthreads();
    for (int s = 128; s > 0; s >>= 1) {
        if (tid < s) red[tid] = fmaxf(red[tid], red[tid + s]);
        __syncthreads();
    }
    m = red[0]; __syncthreads();

    float sum = 0.f;
    for (int i = tid; i < L; i += 256) sum += __expf(g_attn[b * L + i] - m);
    red[tid] = sum; __syncthreads();
    for (int s = 128; s > 0; s >>= 1) {
        if (tid < s) red[tid] += red[tid + s];
        __syncthreads();
    }
    float inv = 1.f / red[0];

    for (int i = tid; i < L; i += 256) {
        float v = __expf(g_attn[b * L + i] - m) * inv;
        g_attn[b * L + i] = v;
        if (out_attn) out_attn[b * L + i] = v;
    }
}

// ---------------- K4: context[b,h] = sum_l a[b,l] * enc[l,b,h] -------------------
#define NCH 32              // l-chunks of 64
__global__ void k4_context(const float* __restrict__ enc)
{
    int b = blockIdx.x / NCH;
    int c = blockIdx.x % NCH;
    int h = threadIdx.x;                        // 256 threads
    __shared__ float s_a[64];
    int l0 = c * 64;
    if (h < 64) s_a[h] = g_attn[b * L + l0 + h];
    __syncthreads();

    const float* base = enc + (size_t)l0 * B * H + (size_t)b * H + h;
    // 4 independent accumulator chains -> more outstanding loads (MLP)
    float a0 = 0.f, a1 = 0.f, a2 = 0.f, a3 = 0.f;
    #pragma unroll
    for (int i = 0; i < 64; i += 4) {
        a0 += s_a[i + 0] * base[(size_t)(i + 0) * B * H];
        a1 += s_a[i + 1] * base[(size_t)(i + 1) * B * H];
        a2 += s_a[i + 2] * base[(size_t)(i + 2) * B * H];
        a3 += s_a[i + 3] * base[(size_t)(i + 3) * B * H];
    }
    atomicAdd(&g_ctx[b * H + h], (a0 + a1) + (a2 + a3));
}

// ---------------- K5: GRU matvecs gi, gh (warp per (j,b)) ------------------------
__global__ void k5_gru(const float* __restrict__ Wih, const float* __restrict__ Whh,
                       const float* __restrict__ bih, const float* __restrict__ bhh,
                       const float* __restrict__ hidden)
{
    int gw   = (blockIdx.x * blockDim.x + threadIdx.x) >> 5;
    int lane = threadIdx.x & 31;
    int j = gw >> 6;        // consecutive warps share j -> weight rows hit L1/L2
    int b = gw & 63;

    const float* wi = Wih + (size_t)j * H2;
    const float* wh = Whh + (size_t)j * H;
    float a1 = 0.f, a2 = 0.f;
    #pragma unroll
    for (int c = 0; c < 8; c++) {
        int k = c * 32 + lane;
        a1 += wi[k]     * g_emb[b * H + k];
        a1 += wi[H + k] * g_ctx[b * H + k];
        a2 += wh[k]     * hidden[b * H + k];
    }
    #pragma unroll
    for (int o = 16; o > 0; o >>= 1) {
        a1 += __shfl_down_sync(0xffffffffu, a1, o);
        a2 += __shfl_down_sync(0xffffffffu, a2, o);
    }
    if (lane == 0) {
        g_gi[b * H3 + j] = a1 + bih[j];
        g_gh[b * H3 + j] = a2 + bhh[j];
    }
}

// ---------------- K6: gates + h_new + build yT[k][b] = [h_new; ctx] --------------
__global__ void k6_gates(const float* __restrict__ hidden, float* __restrict__ out_h)
{
    int idx = blockIdx.x * 256 + threadIdx.x;   // B*H threads
    int b = idx >> 8, j = idx & 255;
    float gir = g_gi[b * H3 + j],          ghr = g_gh[b * H3 + j];
    float giz = g_gi[b * H3 + H + j],      ghz = g_gh[b * H3 + H + j];
    float gin = g_gi[b * H3 + 2 * H + j],  ghn = g_gh[b * H3 + 2 * H + j];
    float r = 1.f / (1.f + __expf(-(gir + ghr)));
    float z = 1.f / (1.f + __expf(-(giz + ghz)));
    float n = tanhf(gin + r * ghn);
    float hn = (1.f - z) * n + z * hidden[idx];
    if (out_h) out_h[idx] = hn;
    g_yT[j * B + b]       = hn;          // k = j       (h_new part)
    g_yT[(H + j) * B + b] = g_ctx[idx];  // k = H + j   (ctx part)
}

// ---------------- K7: logits[b,v] = y[b,:] . out_W[v,:] + out_b[v] ---------------
// 250 blocks x 128 v. y[k][b] staged in 128KB smem. Thread tile: 8 b x 4 v,
// b handled as 4 f32x2 pairs -> packed fma.rn.f32x2 (2 FMA / issue slot).
#define SOUT_PITCH 129
__device__ __forceinline__ ull fma2(ull a, ull x, ull c) {
    asm("fma.rn.f32x2 %0, %1, %2, %3;" : "=l"(a) : "l"(x), "l"(c), "l"(a));
    return a;
}
__device__ __forceinline__ ull pack2(float w) {
    ull r;
    asm("mov.b64 %0, {%1, %1};" : "=l"(r) : "f"(w));
    return r;
}
__device__ __forceinline__ float getc(float4 v, int c) {
    return c == 0 ? v.x : (c == 1 ? v.y : (c == 2 ? v.z : v.w));
}

__global__ __launch_bounds__(256) void k7_logits(const float* __restrict__ outW,
                                                 const float* __restrict__ outb)
{
    extern __shared__ float s_y[];              // [512][64] = 128KB
    int tid = threadIdx.x;
    {
        const float4* src = (const float4*)g_yT;
        float4* dst = (float4*)s_y;
        #pragma unroll
        for (int i = 0; i < (H2 * B / 4) / 256; i++)
            dst[tid + 256 * i] = src[tid + 256 * i];
    }
    __syncthreads();

    int tb = tid & 7;                           // 8 threads along b (8 b each)
    int tv = tid >> 3;                          // 32 threads along v (4 v each)
    int v0 = blockIdx.x * 128 + tv * 4;
    int b0 = tb * 8;

    const float4* wp0 = (const float4*)(outW + (size_t)(v0 + 0) * H2);
    const float4* wp1 = (const float4*)(outW + (size_t)(v0 + 1) * H2);
    const float4* wp2 = (const float4*)(outW + (size_t)(v0 + 2) * H2);
    const float4* wp3 = (const float4*)(outW + (size_t)(v0 + 3) * H2);

    ull acc[4][4];                              // [j][b-pair]
    #pragma unroll
    for (int j = 0; j < 4; j++)
        #pragma unroll
        for (int p = 0; p < 4; p++) acc[j][p] = 0ull;

    #pragma unroll 2
    for (int q = 0; q < H2 / 4; q++) {
        float4 wv0 = wp0[q];
        float4 wv1 = wp1[q];
        float4 wv2 = wp2[q];
        float4 wv3 = wp3[q];
        #pragma unroll
        for (int kk = 0; kk < 4; kk++) {
            int k = q * 4 + kk;
            const ulonglong2* yp = (const ulonglong2*)(s_y + k * B + b0);
            ulonglong2 ya = yp[0];
            ulonglong2 yb = yp[1];
            ull y2[4] = { ya.x, ya.y, yb.x, yb.y };
            ull w20 = pack2(getc(wv0, kk));
            ull w21 = pack2(getc(wv1, kk));
            ull w22 = pack2(getc(wv2, kk));
            ull w23 = pack2(getc(wv3, kk));
            #pragma unroll
            for (int p = 0; p < 4; p++) {
                acc[0][p] = fma2(acc[0][p], w20, y2[p]);
                acc[1][p] = fma2(acc[1][p], w21, y2[p]);
                acc[2][p] = fma2(acc[2][p], w22, y2[p]);
                acc[3][p] = fma2(acc[3][p], w23, y2[p]);
            }
        }
    }

    // epilogue: stage to smem (pitch 129 -> <=2-way conflicts), coalesced f4 out
    __syncthreads();
    float* s_out = s_y;                         // reuse: 64*129*4 = 33KB
    float bb[4];
    #pragma unroll
    for (int j = 0; j < 4; j++) bb[j] = outb[v0 + j];
    #pragma unroll
    for (int j = 0; j < 4; j++)
        #pragma unroll
        for (int p = 0; p < 4; p++) {
            float lo = __uint_as_float((unsigned)(acc[j][p] & 0xffffffffull));
            float hi = __uint_as_float((unsigned)(acc[j][p] >> 32));
            int vl = tv * 4 + j;
            s_out[(b0 + 2 * p + 0) * SOUT_PITCH + vl] = lo + bb[j];
            s_out[(b0 + 2 * p + 1) * SOUT_PITCH + vl] = hi + bb[j];
        }
    __syncthreads();

    // copy 64 x 128 tile to g_logits, coalesced float4 stores
    #pragma unroll
    for (int it = 0; it < (B * 128 / 4) / 256; it++) {
        int i = tid + it * 256;
        int vl4 = i & 31;                       // float4 index along v
        int b = i >> 5;
        const float* s = s_out + b * SOUT_PITCH + vl4 * 4;
        float4 val = make_float4(s[0], s[1], s[2], s[3]);
        *(float4*)(g_logits + (size_t)b * V + blockIdx.x * 128 + vl4 * 4) = val;
    }
}

// ---------------- K8: log_softmax over V per batch --------------------------------
__global__ void k8_logsoftmax(float* __restrict__ out)
{
    int b = blockIdx.x, tid = threadIdx.x;      // 512 threads
    __shared__ float red[512];
    const float* row = g_logits + (size_t)b * V;

    float m = -INFINITY;
    for (int i = tid; i < V; i += 512) m = fmaxf(m, row[i]);
    red[tid] = m; __syncthreads();
    for (int s = 256; s > 0; s >>= 1) {
        if (tid < s) red[tid] = fmaxf(red[tid], red[tid + s]);
        __syncthreads();
    }
    m = red[0]; __syncthreads();

    float sum = 0.f;
    for (int i = tid; i < V; i += 512) sum += __expf(row[i] - m);
    red[tid] = sum; __syncthreads();
    for (int s = 256; s > 0; s >>= 1) {
        if (tid < s) red[tid] += red[tid + s];
        __syncthreads();
    }
    float lse = m + logf(red[0]);

    float* orow = out + (size_t)b * V;
    for (int i = tid; i < V; i += 512) orow[i] = row[i] - lse;
}

// ---------------- host launch ------------------------------------------------------
extern "C" void kernel_launch(void* const* d_in, const int* in_sizes, int n_in,
                              void* d_out, int out_size)
{
    int s = (n_in >= 14 && in_sizes[3] == 1) ? 0 : -1;
    const int*   input    = (const int*)  d_in[0];
    const float* hidden   = (const float*)d_in[1];
    const float* enc      = (const float*)d_in[2];
    const float* emb      = (const float*)d_in[4 + s];
    const float* attn_W   = (const float*)d_in[5 + s];
    const float* attn_b   = (const float*)d_in[6 + s];
    const float* flatten  = (const float*)d_in[7 + s];
    const float* Wih      = (const float*)d_in[8 + s];
    const float* Whh      = (const float*)d_in[9 + s];
    const float* bih      = (const float*)d_in[10 + s];
    const float* bhh      = (const float*)d_in[11 + s];
    const float* outW     = (const float*)d_in[12 + s];
    const float* outb     = (const float*)d_in[13 + s];

    float* dout     = (float*)d_out;
    float* out_h    = (out_size >= B * V + B * H) ? dout + B * V : nullptr;
    float* out_attn = (out_size >= B * V + B * H + B * L) ? dout + B * V + B * H : nullptr;

    k1_prep<<<1, 512>>>(attn_W, attn_b, flatten, hidden, input, emb);
    k2_energy<<<(L * B) / 8, 256>>>(enc);
    k3_softmax<<<B, 256>>>(out_attn);
    k4_context<<<B * NCH, 256>>>(enc);
    k5_gru<<<(B * H3) / 8, 256>>>(Wih, Whh, bih, bhh, hidden);
    k6_gates<<<(B * H) / 256, 256>>>(hidden, out_h);

    int smem_k7 = H2 * B * (int)sizeof(float);  // 131072 B
    cudaFuncSetAttribute(k7_logits, cudaFuncAttributeMaxDynamicSharedMemorySize, smem_k7);
    k7_logits<<<V / 128, 256, smem_k7>>>(outW, outb);

    k8_logsoftmax<<<B, 512>>>(dout);
}